// round 12
// baseline (speedup 1.0000x reference)
#include <cuda_runtime.h>

// out[r][c] = posenc(X[r]) . W[3*voxel_ids[p] + c],  r = row_ids[p]
//
//  K1 rank:    pos[p] = atomicAdd(cnt[v],1)  (int4-vectorized, 4 pts/thread)
//  K2 scan:    exclusive scan -> g_binstart; counters self-reset
//  K3 scatter: g_pts[binstart[v]+pos[p]] = float4(x, bits(r))  (2 pts/thread)
//  K4 main:    1 CTA per voxel, 2 points/thread sharing one set of weight
//              loads (LDS/point halved, 6 independent FMA chains), base
//              sincos + double-angle recurrence, reg cap (256,4).

#define NUM_VOXELS 512
#define NPTS_MAX (1 << 18)
#define PAD 32                    // counter stride in ints = 128 B

__device__ int    g_cnt[NUM_VOXELS * PAD];   // zero-init; self-reset by K2
__device__ int    g_pos[NPTS_MAX];
__device__ int    g_binstart[NUM_VOXELS + 1];
__device__ float4 g_pts[NPTS_MAX];

// ---- K1: per-point rank within its voxel ----
__global__ void __launch_bounds__(256)
rank_kernel(const int* __restrict__ voxel_ids, int n)
{
    int i4 = blockIdx.x * 256 + threadIdx.x;
    int p = i4 * 4;
    if (p + 3 < n) {
        int4 v4 = *reinterpret_cast<const int4*>(voxel_ids + p);
        int4 o;
        o.x = atomicAdd(&g_cnt[v4.x * PAD], 1);
        o.y = atomicAdd(&g_cnt[v4.y * PAD], 1);
        o.z = atomicAdd(&g_cnt[v4.z * PAD], 1);
        o.w = atomicAdd(&g_cnt[v4.w * PAD], 1);
        *reinterpret_cast<int4*>(g_pos + p) = o;
    } else {
        for (int q = p; q < n && q >= 0; ++q)
            g_pos[q] = atomicAdd(&g_cnt[voxel_ids[q] * PAD], 1);
    }
}

// ---- K2: scan counts -> binstart; self-reset counters ----
__global__ void __launch_bounds__(NUM_VOXELS)
scan_kernel(int n)
{
    __shared__ int sh[NUM_VOXELS];
    const int t = threadIdx.x;
    const int val = g_cnt[t * PAD];
    g_cnt[t * PAD] = 0;
    sh[t] = val;
    __syncthreads();
#pragma unroll
    for (int off = 1; off < NUM_VOXELS; off <<= 1) {
        int x = sh[t];
        if (t >= off) x += sh[t - off];
        __syncthreads();
        sh[t] = x;
        __syncthreads();
    }
    g_binstart[t] = sh[t] - val;
    if (t == NUM_VOXELS - 1) g_binstart[NUM_VOXELS] = n;
}

// ---- K3: scatter payload (2 points/thread for MLP) ----
__global__ void __launch_bounds__(256)
scatter_kernel(const float* __restrict__ X,
               const int* __restrict__ row_ids,
               const int* __restrict__ voxel_ids,
               int n)
{
    int p = (blockIdx.x * 256 + threadIdx.x) * 2;
    if (p + 1 < n) {
        const int va = voxel_ids[p],   vb = voxel_ids[p + 1];
        const int qa = g_pos[p],       qb = g_pos[p + 1];
        const int ra = row_ids[p],     rb = row_ids[p + 1];
        float4 a, b;
        a.x = X[3 * ra + 0]; a.y = X[3 * ra + 1]; a.z = X[3 * ra + 2];
        a.w = __int_as_float(ra);
        b.x = X[3 * rb + 0]; b.y = X[3 * rb + 1]; b.z = X[3 * rb + 2];
        b.w = __int_as_float(rb);
        g_pts[g_binstart[va] + qa] = a;
        g_pts[g_binstart[vb] + qb] = b;
    } else if (p < n) {
        const int v = voxel_ids[p];
        const int r = row_ids[p];
        float4 a;
        a.x = X[3 * r + 0]; a.y = X[3 * r + 1]; a.z = X[3 * r + 2];
        a.w = __int_as_float(r);
        g_pts[g_binstart[v] + g_pos[p]] = a;
    }
}

// ---- K4: main — 1 CTA/voxel, 2 points/thread, shared weight loads ----
__global__ void __launch_bounds__(256, 4)
voxel_main_kernel(const float* __restrict__ W,
                  float* __restrict__ out)
{
    __shared__ float2 Wp[3][32];     // (sin,cos) weight pairs, angle a=3f+d
    __shared__ float  Wraw[3][4];    // raw x weights
    const int v = blockIdx.x;
    const int t = threadIdx.x;

    if (t < 90) {
        const int c = t / 30, a = t - 30 * c;
        const int f = a / 3, d = a - 3 * f;
        const float* row = W + (3 * v + c) * 63;
        Wp[c][a] = make_float2(row[3 + 6 * f + d], row[3 + 6 * f + 3 + d]);
    } else if (t < 99) {
        const int u = t - 90;
        const int c = u / 3, d = u - 3 * c;
        Wraw[c][d] = W[(3 * v + c) * 63 + d];
    }
    __syncthreads();

    const int start = g_binstart[v];
    const int cnt   = g_binstart[v + 1] - start;

    for (int base = 0; base < cnt; base += 512) {
        const int iA = base + t;
        const int iB = iA + 256;
        const bool hasA = (iA < cnt);
        const bool hasB = (iB < cnt);
        const float4 payA = g_pts[start + (hasA ? iA : 0)];
        const float4 payB = g_pts[start + (hasB ? iB : 0)];

        const float xA0 = payA.x, xA1 = payA.y, xA2 = payA.z;
        const float xB0 = payB.x, xB1 = payB.y, xB2 = payB.z;

        float aA0 = xA0 * Wraw[0][0];
        aA0 = fmaf(xA1, Wraw[0][1], aA0); aA0 = fmaf(xA2, Wraw[0][2], aA0);
        float aA1 = xA0 * Wraw[1][0];
        aA1 = fmaf(xA1, Wraw[1][1], aA1); aA1 = fmaf(xA2, Wraw[1][2], aA1);
        float aA2 = xA0 * Wraw[2][0];
        aA2 = fmaf(xA1, Wraw[2][1], aA2); aA2 = fmaf(xA2, Wraw[2][2], aA2);
        float aB0 = xB0 * Wraw[0][0];
        aB0 = fmaf(xB1, Wraw[0][1], aB0); aB0 = fmaf(xB2, Wraw[0][2], aB0);
        float aB1 = xB0 * Wraw[1][0];
        aB1 = fmaf(xB1, Wraw[1][1], aB1); aB1 = fmaf(xB2, Wraw[1][2], aB1);
        float aB2 = xB0 * Wraw[2][0];
        aB2 = fmaf(xB1, Wraw[2][1], aB2); aB2 = fmaf(xB2, Wraw[2][2], aB2);

        // base angles (f=0)
        float sA0, cA0, sA1, cA1, sA2, cA2;
        float sB0, cB0, sB1, cB1, sB2, cB2;
        __sincosf(xA0, &sA0, &cA0);
        __sincosf(xA1, &sA1, &cA1);
        __sincosf(xA2, &sA2, &cA2);
        __sincosf(xB0, &sB0, &cB0);
        __sincosf(xB1, &sB1, &cB1);
        __sincosf(xB2, &sB2, &cB2);

#pragma unroll 2
        for (int f = 0; f < 10; ++f) {
            const int a = 3 * f;
            // one set of weight loads feeds BOTH points
            const float2 w00 = Wp[0][a], w01 = Wp[0][a + 1], w02 = Wp[0][a + 2];
            const float2 w10 = Wp[1][a], w11 = Wp[1][a + 1], w12 = Wp[1][a + 2];
            const float2 w20 = Wp[2][a], w21 = Wp[2][a + 1], w22 = Wp[2][a + 2];

            aA0 = fmaf(sA0, w00.x, aA0); aA0 = fmaf(cA0, w00.y, aA0);
            aA0 = fmaf(sA1, w01.x, aA0); aA0 = fmaf(cA1, w01.y, aA0);
            aA0 = fmaf(sA2, w02.x, aA0); aA0 = fmaf(cA2, w02.y, aA0);
            aB0 = fmaf(sB0, w00.x, aB0); aB0 = fmaf(cB0, w00.y, aB0);
            aB0 = fmaf(sB1, w01.x, aB0); aB0 = fmaf(cB1, w01.y, aB0);
            aB0 = fmaf(sB2, w02.x, aB0); aB0 = fmaf(cB2, w02.y, aB0);

            aA1 = fmaf(sA0, w10.x, aA1); aA1 = fmaf(cA0, w10.y, aA1);
            aA1 = fmaf(sA1, w11.x, aA1); aA1 = fmaf(cA1, w11.y, aA1);
            aA1 = fmaf(sA2, w12.x, aA1); aA1 = fmaf(cA2, w12.y, aA1);
            aB1 = fmaf(sB0, w10.x, aB1); aB1 = fmaf(cB0, w10.y, aB1);
            aB1 = fmaf(sB1, w11.x, aB1); aB1 = fmaf(cB1, w11.y, aB1);
            aB1 = fmaf(sB2, w12.x, aB1); aB1 = fmaf(cB2, w12.y, aB1);

            aA2 = fmaf(sA0, w20.x, aA2); aA2 = fmaf(cA0, w20.y, aA2);
            aA2 = fmaf(sA1, w21.x, aA2); aA2 = fmaf(cA1, w21.y, aA2);
            aA2 = fmaf(sA2, w22.x, aA2); aA2 = fmaf(cA2, w22.y, aA2);
            aB2 = fmaf(sB0, w20.x, aB2); aB2 = fmaf(cB0, w20.y, aB2);
            aB2 = fmaf(sB1, w21.x, aB2); aB2 = fmaf(cB1, w21.y, aB2);
            aB2 = fmaf(sB2, w22.x, aB2); aB2 = fmaf(cB2, w22.y, aB2);

            if (f < 9) {   // double-angle: s'=2sc, c'=c^2-s^2
                float ts, tc;
                ts = sA0 * cA0; tc = fmaf(cA0, cA0, -(sA0 * sA0)); sA0 = ts + ts; cA0 = tc;
                ts = sA1 * cA1; tc = fmaf(cA1, cA1, -(sA1 * sA1)); sA1 = ts + ts; cA1 = tc;
                ts = sA2 * cA2; tc = fmaf(cA2, cA2, -(sA2 * sA2)); sA2 = ts + ts; cA2 = tc;
                ts = sB0 * cB0; tc = fmaf(cB0, cB0, -(sB0 * sB0)); sB0 = ts + ts; cB0 = tc;
                ts = sB1 * cB1; tc = fmaf(cB1, cB1, -(sB1 * sB1)); sB1 = ts + ts; cB1 = tc;
                ts = sB2 * cB2; tc = fmaf(cB2, cB2, -(sB2 * sB2)); sB2 = ts + ts; cB2 = tc;
            }
        }

        if (hasA) {
            const int r = __float_as_int(payA.w);
            out[3 * r + 0] = aA0; out[3 * r + 1] = aA1; out[3 * r + 2] = aA2;
        }
        if (hasB) {
            const int r = __float_as_int(payB.w);
            out[3 * r + 0] = aB0; out[3 * r + 1] = aB1; out[3 * r + 2] = aB2;
        }
    }
}

extern "C" void kernel_launch(void* const* d_in, const int* in_sizes, int n_in,
                              void* d_out, int out_size)
{
    const float* X         = (const float*)d_in[0];
    const float* W         = (const float*)d_in[1];
    const int*   row_ids   = (const int*)d_in[2];
    const int*   voxel_ids = (const int*)d_in[3];
    float*       out       = (float*)d_out;

    const int n = in_sizes[0] / 3;               // N_POINTS
    rank_kernel<<<((n + 3) / 4 + 255) / 256, 256>>>(voxel_ids, n);
    scan_kernel<<<1, NUM_VOXELS>>>(n);
    scatter_kernel<<<((n + 1) / 2 + 255) / 256, 256>>>(X, row_ids, voxel_ids, n);
    voxel_main_kernel<<<NUM_VOXELS, 256>>>(W, out);
}